// round 1
// baseline (speedup 1.0000x reference)
#include <cuda_runtime.h>

// Problem constants
#define BDIM   64
#define NDIM   32
#define DDIM   512
#define NPAIR  992                 // 32*31 ordered pairs
#define MROWS  (BDIM * NPAIR)     // 63488 output rows
#define BNROWS (BDIM * NDIM)      // 2048 person rows

// GEMM tiling
#define BM 128
#define BN 128
#define BK 8
#define TM 8
#define TN 8
#define NTHREADS 256

// Scratch: P[bn][c], c<512 -> P1 (f @ W1a^T + b1), c>=512 -> P2 (f @ W1b^T)
__device__ float g_P[(size_t)BNROWS * 1024];

// ---------------------------------------------------------------------------
// Kernel A: per-person partial products.
//   P[bn, c] = sum_k F[bn,k] * W1[c&511, (c>>9)*512 + k]  (+ b1 if c<512)
// M=2048, N=1024, K=512.
// ---------------------------------------------------------------------------
__global__ __launch_bounds__(NTHREADS, 2)
void k_partial(const float* __restrict__ F, const float* __restrict__ W1,
               const float* __restrict__ b1)
{
    __shared__ float As[BK][BM + 4];
    __shared__ float Bs[BK][BN + 4];

    const int tid = threadIdx.x;
    const int tx = tid & 15;         // 0..15 -> col group
    const int ty = tid >> 4;         // 0..15 -> row group
    const int rowBase = blockIdx.y * BM;
    const int colBase = blockIdx.x * BN;

    const int ldRow = tid >> 1;          // 0..127
    const int ldK   = (tid & 1) * 4;     // 0 or 4

    float acc[TM][TN];
#pragma unroll
    for (int m = 0; m < TM; ++m)
#pragma unroll
        for (int n = 0; n < TN; ++n) acc[m][n] = 0.0f;

    const int c = colBase + ldRow;
    const float* wrow = W1 + (size_t)(c & 511) * 1024 + ((c >> 9) << 9);
    const float* arow = F  + (size_t)(rowBase + ldRow) * DDIM;

    for (int kt = 0; kt < DDIM; kt += BK) {
        float4 av = *reinterpret_cast<const float4*>(arow + kt + ldK);
        float4 bv = *reinterpret_cast<const float4*>(wrow + kt + ldK);
        As[ldK + 0][ldRow] = av.x; As[ldK + 1][ldRow] = av.y;
        As[ldK + 2][ldRow] = av.z; As[ldK + 3][ldRow] = av.w;
        Bs[ldK + 0][ldRow] = bv.x; Bs[ldK + 1][ldRow] = bv.y;
        Bs[ldK + 2][ldRow] = bv.z; Bs[ldK + 3][ldRow] = bv.w;
        __syncthreads();

#pragma unroll
        for (int kk = 0; kk < BK; ++kk) {
            float a[TM], b[TN];
#pragma unroll
            for (int m = 0; m < TM; ++m) a[m] = As[kk][ty * TM + m];
#pragma unroll
            for (int n = 0; n < TN; ++n) b[n] = Bs[kk][tx * TN + n];
#pragma unroll
            for (int m = 0; m < TM; ++m)
#pragma unroll
                for (int n = 0; n < TN; ++n)
                    acc[m][n] = fmaf(a[m], b[n], acc[m][n]);
        }
        __syncthreads();
    }

#pragma unroll
    for (int m = 0; m < TM; ++m) {
        const int row = rowBase + ty * TM + m;
#pragma unroll
        for (int n = 0; n < TN; n += 4) {
            const int cc = colBase + tx * TN + n;
            float4 v;
            v.x = acc[m][n + 0]; v.y = acc[m][n + 1];
            v.z = acc[m][n + 2]; v.w = acc[m][n + 3];
            if (cc < 512) {   // fold b1 into P1 half
                const float4 bb = *reinterpret_cast<const float4*>(b1 + cc);
                v.x += bb.x; v.y += bb.y; v.z += bb.z; v.w += bb.w;
            }
            *reinterpret_cast<float4*>(g_P + (size_t)row * 1024 + cc) = v;
        }
    }
}

// ---------------------------------------------------------------------------
// Kernel B: fused main GEMM.
//   H[r,k] = relu(P1[b,i,k] + P2[b,j,k])   (generated on the fly)
//   out[r,c] = sum_k H[r,k] * W2[c,k] + b2[c]
// M=63488, N=512, K=512.
// ---------------------------------------------------------------------------
__global__ __launch_bounds__(NTHREADS, 2)
void k_main(const float* __restrict__ W2, const float* __restrict__ b2,
            float* __restrict__ out)
{
    __shared__ float As[BK][BM + 4];
    __shared__ float Bs[BK][BN + 4];
    __shared__ int rowI[BM];   // element offset of P1 row
    __shared__ int rowJ[BM];   // element offset of P2 row

    const int tid = threadIdx.x;
    const int tx = tid & 15;
    const int ty = tid >> 4;
    const int rowBase = blockIdx.y * BM;
    const int colBase = blockIdx.x * BN;

    if (tid < BM) {
        const int r  = rowBase + tid;
        const int b  = r / NPAIR;
        const int p  = r - b * NPAIR;
        const int i  = p / 31;
        const int jj = p - i * 31;
        const int j  = jj + (jj >= i ? 1 : 0);
        rowI[tid] = (b * NDIM + i) * 1024;         // P1 half
        rowJ[tid] = (b * NDIM + j) * 1024 + 512;   // P2 half
    }
    __syncthreads();

    const int ldRow = tid >> 1;
    const int ldK   = (tid & 1) * 4;

    const float* p1   = g_P + rowI[ldRow];
    const float* p2   = g_P + rowJ[ldRow];
    const float* wrow = W2 + (size_t)(colBase + ldRow) * DDIM;

    float acc[TM][TN];
#pragma unroll
    for (int m = 0; m < TM; ++m)
#pragma unroll
        for (int n = 0; n < TN; ++n) acc[m][n] = 0.0f;

    for (int kt = 0; kt < DDIM; kt += BK) {
        float4 u = *reinterpret_cast<const float4*>(p1 + kt + ldK);
        float4 v = *reinterpret_cast<const float4*>(p2 + kt + ldK);
        float4 w = *reinterpret_cast<const float4*>(wrow + kt + ldK);
        As[ldK + 0][ldRow] = fmaxf(u.x + v.x, 0.0f);
        As[ldK + 1][ldRow] = fmaxf(u.y + v.y, 0.0f);
        As[ldK + 2][ldRow] = fmaxf(u.z + v.z, 0.0f);
        As[ldK + 3][ldRow] = fmaxf(u.w + v.w, 0.0f);
        Bs[ldK + 0][ldRow] = w.x; Bs[ldK + 1][ldRow] = w.y;
        Bs[ldK + 2][ldRow] = w.z; Bs[ldK + 3][ldRow] = w.w;
        __syncthreads();

#pragma unroll
        for (int kk = 0; kk < BK; ++kk) {
            float a[TM], b[TN];
#pragma unroll
            for (int m = 0; m < TM; ++m) a[m] = As[kk][ty * TM + m];
#pragma unroll
            for (int n = 0; n < TN; ++n) b[n] = Bs[kk][tx * TN + n];
#pragma unroll
            for (int m = 0; m < TM; ++m)
#pragma unroll
                for (int n = 0; n < TN; ++n)
                    acc[m][n] = fmaf(a[m], b[n], acc[m][n]);
        }
        __syncthreads();
    }

#pragma unroll
    for (int m = 0; m < TM; ++m) {
        const int row = rowBase + ty * TM + m;
#pragma unroll
        for (int n = 0; n < TN; n += 4) {
            const int cc = colBase + tx * TN + n;
            const float4 bb = *reinterpret_cast<const float4*>(b2 + cc);
            float4 v;
            v.x = acc[m][n + 0] + bb.x;
            v.y = acc[m][n + 1] + bb.y;
            v.z = acc[m][n + 2] + bb.z;
            v.w = acc[m][n + 3] + bb.w;
            *reinterpret_cast<float4*>(out + (size_t)row * DDIM + cc) = v;
        }
    }
}

// ---------------------------------------------------------------------------
extern "C" void kernel_launch(void* const* d_in, const int* in_sizes, int n_in,
                              void* d_out, int out_size)
{
    const float* F  = (const float*)d_in[0];   // person_feats (64,32,512)
    const float* W1 = (const float*)d_in[1];   // (512, 1024)
    const float* b1 = (const float*)d_in[2];   // (512,)
    const float* W2 = (const float*)d_in[3];   // (512, 512)
    const float* b2 = (const float*)d_in[4];   // (512,)
    float* out = (float*)d_out;                // (64, 992, 512)

    dim3 gA(1024 / BN, BNROWS / BM);   // (8, 16)
    k_partial<<<gA, NTHREADS>>>(F, W1, b1);

    dim3 gB(DDIM / BN, MROWS / BM);    // (4, 496)
    k_main<<<gB, NTHREADS>>>(W2, b2, out);
}

// round 3
// speedup vs baseline: 1.5899x; 1.5899x over previous
#include <cuda_runtime.h>
#include <cuda_bf16.h>
#include <cstdint>

// ---------------------------------------------------------------------------
// Problem constants
#define BDIM   64
#define NDIM   32
#define DDIM   512
#define NPAIR  992                 // 32*31 ordered pairs
#define MROWS  (BDIM * NPAIR)      // 63488 output rows
#define BNROWS (BDIM * NDIM)       // 2048 person rows

// Scratch
__device__ float g_P[(size_t)BNROWS * 1024];                    // 8 MB partials
__device__ __align__(16) unsigned short g_W2h[512 * 512];       // bf16 hi of W2
__device__ __align__(16) unsigned short g_W2l[512 * 512];       // bf16 lo of W2

// ---------------------------------------------------------------------------
// Helpers
// ---------------------------------------------------------------------------
__device__ __forceinline__ uint32_t smem_u32(const void* p) {
    uint32_t a;
    asm("{ .reg .u64 t; cvta.to.shared.u64 t, %1; cvt.u32.u64 %0, t; }"
        : "=r"(a) : "l"(p));
    return a;
}

__device__ __forceinline__ void ldsm_x4(uint32_t* r, uint32_t addr) {
    asm volatile("ldmatrix.sync.aligned.m8n8.x4.shared.b16 {%0,%1,%2,%3},[%4];"
        : "=r"(r[0]), "=r"(r[1]), "=r"(r[2]), "=r"(r[3]) : "r"(addr));
}
__device__ __forceinline__ void ldsm_x2(uint32_t* r, uint32_t addr) {
    asm volatile("ldmatrix.sync.aligned.m8n8.x2.shared.b16 {%0,%1},[%2];"
        : "=r"(r[0]), "=r"(r[1]) : "r"(addr));
}
__device__ __forceinline__ void mma_bf16(float* d, const uint32_t* a, const uint32_t* b) {
    asm volatile(
        "mma.sync.aligned.m16n8k16.row.col.f32.bf16.bf16.f32 "
        "{%0,%1,%2,%3},{%4,%5,%6,%7},{%8,%9},{%0,%1,%2,%3};"
        : "+f"(d[0]), "+f"(d[1]), "+f"(d[2]), "+f"(d[3])
        : "r"(a[0]), "r"(a[1]), "r"(a[2]), "r"(a[3]), "r"(b[0]), "r"(b[1]));
}
__device__ __forceinline__ void cp_async16(uint32_t dst, const void* src) {
    asm volatile("cp.async.cg.shared.global [%0], [%1], 16;"
        :: "r"(dst), "l"(__cvta_generic_to_global(src)) : "memory");
}
#define CP_COMMIT() asm volatile("cp.async.commit_group;" ::: "memory")
#define CP_WAIT0()  asm volatile("cp.async.wait_group 0;" ::: "memory")

// bf16 hi/lo split of two floats -> two packed bf16x2 words
__device__ __forceinline__ void split2(float x0, float x1, uint32_t& h, uint32_t& l) {
    __nv_bfloat16 h0 = __float2bfloat16(x0);
    __nv_bfloat16 h1 = __float2bfloat16(x1);
    h = (uint32_t)__bfloat16_as_ushort(h0) | ((uint32_t)__bfloat16_as_ushort(h1) << 16);
    __nv_bfloat16 l0 = __float2bfloat16(x0 - __bfloat162float(h0));
    __nv_bfloat16 l1 = __float2bfloat16(x1 - __bfloat162float(h1));
    l = (uint32_t)__bfloat16_as_ushort(l0) | ((uint32_t)__bfloat16_as_ushort(l1) << 16);
}

// ---------------------------------------------------------------------------
// Kernel A: per-person partial products (fp32 SGEMM).
//   P[bn, c] = sum_k F[bn,k] * W1[c&511, (c>>9)*512 + k]  (+ b1 if c<512)
// ---------------------------------------------------------------------------
#define BM 128
#define BN 128
#define BK 8
#define TM 8
#define TN 8

__global__ __launch_bounds__(256, 2)
void k_partial(const float* __restrict__ F, const float* __restrict__ W1,
               const float* __restrict__ b1)
{
    __shared__ float As[BK][BM + 4];
    __shared__ float Bs[BK][BN + 4];

    const int tid = threadIdx.x;
    const int tx = tid & 15;
    const int ty = tid >> 4;
    const int rowBase = blockIdx.y * BM;
    const int colBase = blockIdx.x * BN;

    const int ldRow = tid >> 1;
    const int ldK   = (tid & 1) * 4;

    float acc[TM][TN];
#pragma unroll
    for (int m = 0; m < TM; ++m)
#pragma unroll
        for (int n = 0; n < TN; ++n) acc[m][n] = 0.0f;

    const int c = colBase + ldRow;
    const float* wrow = W1 + (size_t)(c & 511) * 1024 + ((c >> 9) << 9);
    const float* arow = F  + (size_t)(rowBase + ldRow) * DDIM;

    for (int kt = 0; kt < DDIM; kt += BK) {
        float4 av = *reinterpret_cast<const float4*>(arow + kt + ldK);
        float4 bv = *reinterpret_cast<const float4*>(wrow + kt + ldK);
        As[ldK + 0][ldRow] = av.x; As[ldK + 1][ldRow] = av.y;
        As[ldK + 2][ldRow] = av.z; As[ldK + 3][ldRow] = av.w;
        Bs[ldK + 0][ldRow] = bv.x; Bs[ldK + 1][ldRow] = bv.y;
        Bs[ldK + 2][ldRow] = bv.z; Bs[ldK + 3][ldRow] = bv.w;
        __syncthreads();

#pragma unroll
        for (int kk = 0; kk < BK; ++kk) {
            float a[TM], b[TN];
#pragma unroll
            for (int m = 0; m < TM; ++m) a[m] = As[kk][ty * TM + m];
#pragma unroll
            for (int n = 0; n < TN; ++n) b[n] = Bs[kk][tx * TN + n];
#pragma unroll
            for (int m = 0; m < TM; ++m)
#pragma unroll
                for (int n = 0; n < TN; ++n)
                    acc[m][n] = fmaf(a[m], b[n], acc[m][n]);
        }
        __syncthreads();
    }

#pragma unroll
    for (int m = 0; m < TM; ++m) {
        const int row = rowBase + ty * TM + m;
#pragma unroll
        for (int n = 0; n < TN; n += 4) {
            const int cc = colBase + tx * TN + n;
            float4 v;
            v.x = acc[m][n + 0]; v.y = acc[m][n + 1];
            v.z = acc[m][n + 2]; v.w = acc[m][n + 3];
            if (cc < 512) {
                const float4 bb = *reinterpret_cast<const float4*>(b1 + cc);
                v.x += bb.x; v.y += bb.y; v.z += bb.z; v.w += bb.w;
            }
            *reinterpret_cast<float4*>(g_P + (size_t)row * 1024 + cc) = v;
        }
    }
}

// ---------------------------------------------------------------------------
// Split W2 into bf16 hi/lo
// ---------------------------------------------------------------------------
__global__ __launch_bounds__(256)
void k_splitw2(const float* __restrict__ W2)
{
    int idx = blockIdx.x * 256 + threadIdx.x;
    float4 v = reinterpret_cast<const float4*>(W2)[idx];
    uint32_t h0, l0, h1, l1;
    split2(v.x, v.y, h0, l0);
    split2(v.z, v.w, h1, l1);
    reinterpret_cast<uint2*>(g_W2h)[idx] = make_uint2(h0, h1);
    reinterpret_cast<uint2*>(g_W2l)[idx] = make_uint2(l0, l1);
}

// ---------------------------------------------------------------------------
// Kernel B: split-bf16 HMMA GEMM (mma.sync m16n8k16).
//   out[r, n] = relu(P1 + P2) @ W2^T + b2
// CTA 128(M) x 128(N), 8 warps 4x2, warp tile 32x64. K=512 in 8 chunks of 64.
// Stage (64KB): Ah 16K | Al 16K | Bh 16K | Bl 16K. Double buffered.
// Swizzle: 128B rows, 16B block kb stored at (kb ^ (row&7)).
// ---------------------------------------------------------------------------
#define STG   65536
#define SMEM_DYN (2 * STG + 1024)

__global__ __launch_bounds__(256)
void k_main_mma(const float* __restrict__ b2, float* __restrict__ out)
{
    extern __shared__ char dsm[];
    __shared__ int s_rowI[128], s_rowJ[128];

    const int tid = threadIdx.x;
    const int wid = tid >> 5;
    const int lid = tid & 31;

    uint32_t raw = smem_u32(dsm);
    uint32_t dbase = (raw + 1023u) & ~1023u;
    char* dptr = dsm + (dbase - raw);

    const int rowBase = blockIdx.y * 128;
    const int colBase = blockIdx.x * 128;

    if (tid < 128) {
        int r = rowBase + tid;
        int b = r / NPAIR;
        int p = r - b * NPAIR;
        int i = p / 31;
        int jj = p - i * 31;
        int j = jj + (jj >= i ? 1 : 0);
        s_rowI[tid] = (b * NDIM + i) * 1024;
        s_rowJ[tid] = (b * NDIM + j) * 1024 + 512;
    }
    __syncthreads();

    // ---- producer roles ----
    const int arow  = tid >> 1;       // A: 2 threads per row, 32 floats each
    const int ahalf = tid & 1;
    const float* p1b = g_P + s_rowI[arow] + ahalf * 32;
    const float* p2b = g_P + s_rowJ[arow] + ahalf * 32;
    const uint32_t aswz = (uint32_t)(arow & 7);
    const uint32_t arowoff = (uint32_t)arow * 128;

    const unsigned short* wh = g_W2h + (size_t)(colBase + arow) * 512 + ahalf * 32;
    const unsigned short* wl = g_W2l + (size_t)(colBase + arow) * 512 + ahalf * 32;

    // ---- consumer roles ----
    const int wm = (wid & 3) * 32;    // warp M offset
    const int wn = (wid >> 2) * 64;   // warp N offset

    float acc[2][8][4];
#pragma unroll
    for (int mi = 0; mi < 2; ++mi)
#pragma unroll
        for (int ni = 0; ni < 8; ++ni)
#pragma unroll
            for (int q = 0; q < 4; ++q) acc[mi][ni][q] = 0.0f;

    float af[32];

    // -- A: global load + relu for chunk c into af --
    auto loadA = [&](int c) {
#pragma unroll
        for (int g = 0; g < 8; ++g) {
            float4 u = *reinterpret_cast<const float4*>(p1b + c * 64 + g * 4);
            float4 v = *reinterpret_cast<const float4*>(p2b + c * 64 + g * 4);
            af[4 * g + 0] = fmaxf(u.x + v.x, 0.0f);
            af[4 * g + 1] = fmaxf(u.y + v.y, 0.0f);
            af[4 * g + 2] = fmaxf(u.z + v.z, 0.0f);
            af[4 * g + 3] = fmaxf(u.w + v.w, 0.0f);
        }
    };
    // -- A: split + swizzled store into stage s --
    auto storeA = [&](int s) {
        char* Ah = dptr + s * STG;
        char* Al = Ah + 16384;
#pragma unroll
        for (int g = 0; g < 4; ++g) {
            uint4 hh, ll;
            split2(af[8 * g + 0], af[8 * g + 1], hh.x, ll.x);
            split2(af[8 * g + 2], af[8 * g + 3], hh.y, ll.y);
            split2(af[8 * g + 4], af[8 * g + 5], hh.z, ll.z);
            split2(af[8 * g + 6], af[8 * g + 7], hh.w, ll.w);
            uint32_t kb = (uint32_t)(ahalf * 4 + g);
            uint32_t off = arowoff + ((kb ^ aswz) << 4);
            *reinterpret_cast<uint4*>(Ah + off) = hh;
            *reinterpret_cast<uint4*>(Al + off) = ll;
        }
    };
    // -- B: cp.async into stage s --
    auto loadB = [&](int c, int s) {
        uint32_t Bh = dbase + s * STG + 32768;
#pragma unroll
        for (int g = 0; g < 4; ++g) {
            uint32_t kb = (uint32_t)(ahalf * 4 + g);
            uint32_t off = arowoff + ((kb ^ aswz) << 4);
            cp_async16(Bh + off,         wh + c * 64 + g * 8);
            cp_async16(Bh + 16384 + off, wl + c * 64 + g * 8);
        }
        CP_COMMIT();
    };

    // -- compute one chunk from stage s --
    auto compute = [&](int s) {
        const uint32_t AhB = dbase + s * STG;
        const uint32_t BhB = AhB + 32768;
        const int mrow = lid & 15;
        const int ksel = lid >> 4;       // A: which 16B k-block half
        const int bn_  = lid & 7;
        const int bsel = (lid >> 3) & 1; // B: k-block half (lanes 0-15 matter)
#pragma unroll
        for (int ks = 0; ks < 4; ++ks) {
            uint32_t ah[2][4], al[2][4], bh[8][2], bl[8][2];
#pragma unroll
            for (int mi = 0; mi < 2; ++mi) {
                uint32_t r = (uint32_t)(wm + mi * 16 + mrow);
                uint32_t kb = (uint32_t)(ks * 2 + ksel);
                uint32_t addr = AhB + r * 128 + ((kb ^ (r & 7)) << 4);
                ldsm_x4(ah[mi], addr);
                ldsm_x4(al[mi], addr + 16384);
            }
#pragma unroll
            for (int ni = 0; ni < 8; ++ni) {
                uint32_t n = (uint32_t)(wn + ni * 8 + bn_);
                uint32_t kb = (uint32_t)(ks * 2 + bsel);
                uint32_t addr = BhB + n * 128 + ((kb ^ (n & 7)) << 4);
                ldsm_x2(bh[ni], addr);
                ldsm_x2(bl[ni], addr + 16384);
            }
#pragma unroll
            for (int mi = 0; mi < 2; ++mi)
#pragma unroll
                for (int ni = 0; ni < 8; ++ni) {
                    mma_bf16(acc[mi][ni], ah[mi], bh[ni]);
                    mma_bf16(acc[mi][ni], ah[mi], bl[ni]);
                    mma_bf16(acc[mi][ni], al[mi], bh[ni]);
                }
        }
    };

    // ---- prologue: fill stage 0 with chunk 0 ----
    loadA(0);
    storeA(0);
    loadB(0, 0);
    CP_WAIT0();
    __syncthreads();

    // ---- pipelined main loop ----
    for (int c = 0; c < 8; ++c) {
        const int s = c & 1;
        if (c < 7) {
            loadA(c + 1);          // global loads in flight during MMAs
            loadB(c + 1, 1 - s);   // cp.async in flight during MMAs
        }
        compute(s);
        if (c < 7) {
            storeA(1 - s);
            CP_WAIT0();
        }
        __syncthreads();
    }

    // ---- epilogue: acc + b2 -> out ----
    {
        const int t2 = (lid & 3) * 2;
        const int gg = lid >> 2;
        float2 bb[8];
#pragma unroll
        for (int ni = 0; ni < 8; ++ni)
            bb[ni] = *reinterpret_cast<const float2*>(b2 + colBase + wn + ni * 8 + t2);

#pragma unroll
        for (int mi = 0; mi < 2; ++mi) {
            const int r0 = rowBase + wm + mi * 16 + gg;
#pragma unroll
            for (int ni = 0; ni < 8; ++ni) {
                const int cc = colBase + wn + ni * 8 + t2;
                float2 v0, v1;
                v0.x = acc[mi][ni][0] + bb[ni].x;
                v0.y = acc[mi][ni][1] + bb[ni].y;
                v1.x = acc[mi][ni][2] + bb[ni].x;
                v1.y = acc[mi][ni][3] + bb[ni].y;
                *reinterpret_cast<float2*>(out + (size_t)r0 * 512 + cc) = v0;
                *reinterpret_cast<float2*>(out + (size_t)(r0 + 8) * 512 + cc) = v1;
            }
        }
    }
}

// ---------------------------------------------------------------------------
extern "C" void kernel_launch(void* const* d_in, const int* in_sizes, int n_in,
                              void* d_out, int out_size)
{
    const float* F  = (const float*)d_in[0];   // person_feats (64,32,512)
    const float* W1 = (const float*)d_in[1];   // (512, 1024)
    const float* b1 = (const float*)d_in[2];   // (512,)
    const float* W2 = (const float*)d_in[3];   // (512, 512)
    const float* b2 = (const float*)d_in[4];   // (512,)
    float* out = (float*)d_out;                // (64, 992, 512)

    cudaFuncSetAttribute(k_main_mma, cudaFuncAttributeMaxDynamicSharedMemorySize, SMEM_DYN);

    k_splitw2<<<256, 256>>>(W2);

    dim3 gA(1024 / BN, BNROWS / BM);           // (8, 16)
    k_partial<<<gA, 256>>>(F, W1, b1);

    dim3 gB(4, MROWS / 128);                   // (4, 496)
    k_main_mma<<<gB, 256, SMEM_DYN>>>(b2, out);
}

// round 4
// speedup vs baseline: 2.6506x; 1.6671x over previous
#include <cuda_runtime.h>
#include <cuda_bf16.h>
#include <cstdint>

// ---------------------------------------------------------------------------
// Problem constants
#define BDIM   64
#define NDIM   32
#define DDIM   512
#define NPAIR  992                 // 32*31 ordered pairs
#define MROWS  (BDIM * NPAIR)      // 63488 output rows
#define BNROWS (BDIM * NDIM)       // 2048 person rows

// Scratch (device globals; no allocations allowed)
__device__ float g_P[(size_t)BNROWS * 1024];                      // 8 MB fp32 partials
__device__ __align__(16) unsigned short g_Fh[BNROWS * 512];       // bf16 hi of F
__device__ __align__(16) unsigned short g_Fl[BNROWS * 512];
__device__ __align__(16) unsigned short g_W1h[1024 * 512];        // W1 rearranged [c][k]
__device__ __align__(16) unsigned short g_W1l[1024 * 512];
__device__ __align__(16) unsigned short g_W2h[512 * 512];
__device__ __align__(16) unsigned short g_W2l[512 * 512];
__device__ __align__(16) unsigned short g_Hh[(size_t)MROWS * 512]; // 65 MB
__device__ __align__(16) unsigned short g_Hl[(size_t)MROWS * 512]; // 65 MB

// ---------------------------------------------------------------------------
// Helpers
// ---------------------------------------------------------------------------
__device__ __forceinline__ uint32_t smem_u32(const void* p) {
    uint32_t a;
    asm("{ .reg .u64 t; cvta.to.shared.u64 t, %1; cvt.u32.u64 %0, t; }"
        : "=r"(a) : "l"(p));
    return a;
}
__device__ __forceinline__ void ldsm_x4(uint32_t* r, uint32_t addr) {
    asm volatile("ldmatrix.sync.aligned.m8n8.x4.shared.b16 {%0,%1,%2,%3},[%4];"
        : "=r"(r[0]), "=r"(r[1]), "=r"(r[2]), "=r"(r[3]) : "r"(addr));
}
__device__ __forceinline__ void ldsm_x2(uint32_t* r, uint32_t addr) {
    asm volatile("ldmatrix.sync.aligned.m8n8.x2.shared.b16 {%0,%1},[%2];"
        : "=r"(r[0]), "=r"(r[1]) : "r"(addr));
}
__device__ __forceinline__ void mma_bf16(float* d, const uint32_t* a, const uint32_t* b) {
    asm volatile(
        "mma.sync.aligned.m16n8k16.row.col.f32.bf16.bf16.f32 "
        "{%0,%1,%2,%3},{%4,%5,%6,%7},{%8,%9},{%0,%1,%2,%3};"
        : "+f"(d[0]), "+f"(d[1]), "+f"(d[2]), "+f"(d[3])
        : "r"(a[0]), "r"(a[1]), "r"(a[2]), "r"(a[3]), "r"(b[0]), "r"(b[1]));
}
__device__ __forceinline__ void cp_async16(uint32_t dst, const void* src) {
    asm volatile("cp.async.cg.shared.global [%0], [%1], 16;"
        :: "r"(dst), "l"(__cvta_generic_to_global(src)) : "memory");
}
#define CP_COMMIT() asm volatile("cp.async.commit_group;" ::: "memory")
#define CP_WAIT(n)  asm volatile("cp.async.wait_group %0;" :: "n"(n) : "memory")

// bf16 hi/lo split of two floats -> two packed bf16x2 words
__device__ __forceinline__ void split2(float x0, float x1, uint32_t& h, uint32_t& l) {
    __nv_bfloat16 h0 = __float2bfloat16(x0);
    __nv_bfloat16 h1 = __float2bfloat16(x1);
    h = (uint32_t)__bfloat16_as_ushort(h0) | ((uint32_t)__bfloat16_as_ushort(h1) << 16);
    __nv_bfloat16 l0 = __float2bfloat16(x0 - __bfloat162float(h0));
    __nv_bfloat16 l1 = __float2bfloat16(x1 - __bfloat162float(h1));
    l = (uint32_t)__bfloat16_as_ushort(l0) | ((uint32_t)__bfloat16_as_ushort(l1) << 16);
}

// ---------------------------------------------------------------------------
// Input split kernels
// ---------------------------------------------------------------------------
__global__ __launch_bounds__(256)
void k_w2split(const float* __restrict__ W2)
{
    int idx = blockIdx.x * 256 + threadIdx.x;         // 65536 float4s
    float4 v = reinterpret_cast<const float4*>(W2)[idx];
    uint32_t h0, l0, h1, l1;
    split2(v.x, v.y, h0, l0);
    split2(v.z, v.w, h1, l1);
    reinterpret_cast<uint2*>(g_W2h)[idx] = make_uint2(h0, h1);
    reinterpret_cast<uint2*>(g_W2l)[idx] = make_uint2(l0, l1);
}

__global__ __launch_bounds__(256)
void k_fsplit(const float* __restrict__ F)
{
    int idx = blockIdx.x * 256 + threadIdx.x;         // 262144 float4s
    float4 v = reinterpret_cast<const float4*>(F)[idx];
    uint32_t h0, l0, h1, l1;
    split2(v.x, v.y, h0, l0);
    split2(v.z, v.w, h1, l1);
    reinterpret_cast<uint2*>(g_Fh)[idx] = make_uint2(h0, h1);
    reinterpret_cast<uint2*>(g_Fl)[idx] = make_uint2(l0, l1);
}

// W1' [c][k] = W1[c&511][(c>>9)*512 + k],  c<1024, k<512
__global__ __launch_bounds__(256)
void k_w1split(const float* __restrict__ W1)
{
    int idx = blockIdx.x * 256 + threadIdx.x;         // 131072 float4s
    int L = idx * 4;
    int c = L >> 9;
    int k = L & 511;
    const float4 v = *reinterpret_cast<const float4*>(
        W1 + (size_t)(c & 511) * 1024 + ((c >> 9) << 9) + k);
    uint32_t h0, l0, h1, l1;
    split2(v.x, v.y, h0, l0);
    split2(v.z, v.w, h1, l1);
    reinterpret_cast<uint2*>(g_W1h)[idx] = make_uint2(h0, h1);
    reinterpret_cast<uint2*>(g_W1l)[idx] = make_uint2(l0, l1);
}

// ---------------------------------------------------------------------------
// H split: H[r][k] = relu(P[b*32+i][k] + P[b*32+j][512+k]) -> bf16 hi/lo
// 8 warps per block, one row per warp, 16 elems per lane.
// ---------------------------------------------------------------------------
__global__ __launch_bounds__(256)
void k_hsplit()
{
    const int r   = blockIdx.x * 8 + (threadIdx.x >> 5);
    const int lid = threadIdx.x & 31;
    const int b = r / NPAIR;
    const int p = r - b * NPAIR;
    const int i = p / 31;
    const int jj = p - i * 31;
    const int j = jj + (jj >= i ? 1 : 0);

    const float* p1 = g_P + (size_t)(b * NDIM + i) * 1024 + lid * 16;
    const float* p2 = g_P + (size_t)(b * NDIM + j) * 1024 + 512 + lid * 16;
    unsigned short* hh = g_Hh + (size_t)r * 512 + lid * 16;
    unsigned short* hl = g_Hl + (size_t)r * 512 + lid * 16;

#pragma unroll
    for (int g = 0; g < 2; ++g) {                     // 2 groups of 8 elems
        float4 a0 = *reinterpret_cast<const float4*>(p1 + g * 8);
        float4 a1 = *reinterpret_cast<const float4*>(p1 + g * 8 + 4);
        float4 c0 = *reinterpret_cast<const float4*>(p2 + g * 8);
        float4 c1 = *reinterpret_cast<const float4*>(p2 + g * 8 + 4);
        float x0 = fmaxf(a0.x + c0.x, 0.f), x1 = fmaxf(a0.y + c0.y, 0.f);
        float x2 = fmaxf(a0.z + c0.z, 0.f), x3 = fmaxf(a0.w + c0.w, 0.f);
        float x4 = fmaxf(a1.x + c1.x, 0.f), x5 = fmaxf(a1.y + c1.y, 0.f);
        float x6 = fmaxf(a1.z + c1.z, 0.f), x7 = fmaxf(a1.w + c1.w, 0.f);
        uint4 H, L;
        split2(x0, x1, H.x, L.x);
        split2(x2, x3, H.y, L.y);
        split2(x4, x5, H.z, L.z);
        split2(x6, x7, H.w, L.w);
        *reinterpret_cast<uint4*>(hh + g * 8) = H;
        *reinterpret_cast<uint4*>(hl + g * 8) = L;
    }
}

// ---------------------------------------------------------------------------
// Generic 3-term split-bf16 GEMM:  out = (Ah+Al) @ (Bh+Bl)^T  [+ bias]
// A: [M][512] bf16 row-major (hi/lo), B: [N][512] bf16 row-major (hi/lo).
// CTA tile 128x128, 8 warps 4(M)x2(N), warp 32x64, K in 8 chunks of 64.
// Triple-buffered cp.async stages of 64KB: Ah|Al|Bh|Bl (16KB each).
// Swizzle: 128B rows, 16B block kb stored at (kb ^ (row&7))*16.
// BIAS_MODE: 1 = add bias[c] only when colBase < 512 (gemmA), 2 = always.
// ---------------------------------------------------------------------------
#define STG      65536
#define NSTG     3
#define SMEM_DYN (NSTG * STG + 1024)

template<int BIAS_MODE>
__global__ __launch_bounds__(256, 1)
void k_gemm(const unsigned short* __restrict__ Ah_g,
            const unsigned short* __restrict__ Al_g,
            const unsigned short* __restrict__ Bh_g,
            const unsigned short* __restrict__ Bl_g,
            const float* __restrict__ bias,
            float* __restrict__ out, int outStride)
{
    extern __shared__ char dsm[];
    const int tid = threadIdx.x;
    const int wid = tid >> 5;
    const int lid = tid & 31;

    uint32_t raw = smem_u32(dsm);
    const uint32_t dbase = (raw + 1023u) & ~1023u;

    const int rowBase = blockIdx.y * 128;
    const int colBase = blockIdx.x * 128;

    const unsigned short* Asrc_h = Ah_g + (size_t)rowBase * 512;
    const unsigned short* Asrc_l = Al_g + (size_t)rowBase * 512;
    const unsigned short* Bsrc_h = Bh_g + (size_t)colBase * 512;
    const unsigned short* Bsrc_l = Bl_g + (size_t)colBase * 512;

    // one 128x64 bf16 tile part = 1024 16B chunks; 256 threads x 4
    auto ldt = [&](uint32_t dst, const unsigned short* src, int c) {
#pragma unroll
        for (int g = 0; g < 4; ++g) {
            const int q = tid + 256 * g;
            const int row = q >> 3;
            const int kb  = q & 7;
            const uint32_t off = (uint32_t)row * 128 + (uint32_t)((kb ^ (row & 7)) << 4);
            cp_async16(dst + off, src + (size_t)row * 512 + c * 64 + kb * 8);
        }
    };
    auto loadStage = [&](int c, int s) {
        const uint32_t st = dbase + s * STG;
        ldt(st,         Asrc_h, c);
        ldt(st + 16384, Asrc_l, c);
        ldt(st + 32768, Bsrc_h, c);
        ldt(st + 49152, Bsrc_l, c);
    };

    const int wm = (wid & 3) * 32;
    const int wn = (wid >> 2) * 64;

    float acc[2][8][4];
#pragma unroll
    for (int mi = 0; mi < 2; ++mi)
#pragma unroll
        for (int ni = 0; ni < 8; ++ni)
#pragma unroll
            for (int q = 0; q < 4; ++q) acc[mi][ni][q] = 0.0f;

    auto compute = [&](int s) {
        const uint32_t AhB = dbase + s * STG;
        const uint32_t BhB = AhB + 32768;
        const int mrow = lid & 15;
        const int ksel = lid >> 4;
        const int bn_  = lid & 7;
        const int bsel = (lid >> 3) & 1;
#pragma unroll
        for (int ks = 0; ks < 4; ++ks) {
            uint32_t ah[2][4], al[2][4], bh[8][2], bl[8][2];
#pragma unroll
            for (int mi = 0; mi < 2; ++mi) {
                const uint32_t r = (uint32_t)(wm + mi * 16 + mrow);
                const uint32_t kb = (uint32_t)(ks * 2 + ksel);
                const uint32_t addr = AhB + r * 128 + ((kb ^ (r & 7)) << 4);
                ldsm_x4(ah[mi], addr);
                ldsm_x4(al[mi], addr + 16384);
            }
#pragma unroll
            for (int ni = 0; ni < 8; ++ni) {
                const uint32_t n = (uint32_t)(wn + ni * 8 + bn_);
                const uint32_t kb = (uint32_t)(ks * 2 + bsel);
                const uint32_t addr = BhB + n * 128 + ((kb ^ (n & 7)) << 4);
                ldsm_x2(bh[ni], addr);
                ldsm_x2(bl[ni], addr + 16384);
            }
#pragma unroll
            for (int mi = 0; mi < 2; ++mi)
#pragma unroll
                for (int ni = 0; ni < 8; ++ni) {
                    mma_bf16(acc[mi][ni], ah[mi], bh[ni]);
                    mma_bf16(acc[mi][ni], ah[mi], bl[ni]);
                    mma_bf16(acc[mi][ni], al[mi], bh[ni]);
                }
        }
    };

    // ---- prologue: stages 0,1 in flight ----
    loadStage(0, 0); CP_COMMIT();
    loadStage(1, 1); CP_COMMIT();

    // ---- main loop ----
    for (int c = 0; c < 8; ++c) {
        CP_WAIT(1);                 // chunk c landed
        __syncthreads();            // all warps done with stage (c)%NSTG's prior user
        if (c + 2 < 8) loadStage(c + 2, (c + 2) % NSTG);
        CP_COMMIT();                // empty group when no loads (keeps counts uniform)
        compute(c % NSTG);
    }

    // ---- epilogue ----
    {
        const int t2 = (lid & 3) * 2;
        const int gg = lid >> 2;
        float2 bb[8];
#pragma unroll
        for (int ni = 0; ni < 8; ++ni) {
            if (BIAS_MODE == 2 || colBase < 512)
                bb[ni] = *reinterpret_cast<const float2*>(bias + colBase + wn + ni * 8 + t2);
            else
                bb[ni] = make_float2(0.f, 0.f);
        }
#pragma unroll
        for (int mi = 0; mi < 2; ++mi) {
            const int r0 = rowBase + wm + mi * 16 + gg;
#pragma unroll
            for (int ni = 0; ni < 8; ++ni) {
                const int cc = colBase + wn + ni * 8 + t2;
                float2 v0, v1;
                v0.x = acc[mi][ni][0] + bb[ni].x;
                v0.y = acc[mi][ni][1] + bb[ni].y;
                v1.x = acc[mi][ni][2] + bb[ni].x;
                v1.y = acc[mi][ni][3] + bb[ni].y;
                *reinterpret_cast<float2*>(out + (size_t)r0 * outStride + cc) = v0;
                *reinterpret_cast<float2*>(out + (size_t)(r0 + 8) * outStride + cc) = v1;
            }
        }
    }
}

// ---------------------------------------------------------------------------
extern "C" void kernel_launch(void* const* d_in, const int* in_sizes, int n_in,
                              void* d_out, int out_size)
{
    const float* F  = (const float*)d_in[0];   // person_feats (64,32,512)
    const float* W1 = (const float*)d_in[1];   // (512, 1024)
    const float* b1 = (const float*)d_in[2];   // (512,)
    const float* W2 = (const float*)d_in[3];   // (512, 512)
    const float* b2 = (const float*)d_in[4];   // (512,)
    float* out = (float*)d_out;                // (64, 992, 512)

    cudaFuncSetAttribute(k_gemm<1>, cudaFuncAttributeMaxDynamicSharedMemorySize, SMEM_DYN);
    cudaFuncSetAttribute(k_gemm<2>, cudaFuncAttributeMaxDynamicSharedMemorySize, SMEM_DYN);

    // resolve device-global scratch addresses (host side)
    unsigned short *Fh, *Fl, *W1h, *W1l, *W2h, *W2l, *Hh, *Hl;
    float* P;
    cudaGetSymbolAddress((void**)&Fh,  g_Fh);
    cudaGetSymbolAddress((void**)&Fl,  g_Fl);
    cudaGetSymbolAddress((void**)&W1h, g_W1h);
    cudaGetSymbolAddress((void**)&W1l, g_W1l);
    cudaGetSymbolAddress((void**)&W2h, g_W2h);
    cudaGetSymbolAddress((void**)&W2l, g_W2l);
    cudaGetSymbolAddress((void**)&Hh,  g_Hh);
    cudaGetSymbolAddress((void**)&Hl,  g_Hl);
    cudaGetSymbolAddress((void**)&P,   g_P);

    // 1) split inputs to bf16 hi/lo
    k_w2split<<<256, 256>>>(W2);
    k_fsplit<<<1024, 256>>>(F);
    k_w1split<<<512, 256>>>(W1);

    // 2) P = F @ W1'^T (+ b1 on first 512 cols): M=2048, N=1024
    {
        dim3 g(8, 16);
        k_gemm<1><<<g, 256, SMEM_DYN>>>(Fh, Fl, W1h, W1l, b1, P, 1024);
    }

    // 3) H = split(relu(P1 + P2))
    k_hsplit<<<MROWS / 8, 256>>>();

    // 4) out = H @ W2^T + b2: M=63488, N=512
    {
        dim3 g(4, MROWS / 128);
        k_gemm<2><<<g, 256, SMEM_DYN>>>(Hh, Hl, W2h, W2l, b2, out, 512);
    }
}